// round 3
// baseline (speedup 1.0000x reference)
#include <cuda_runtime.h>

#define N_NODES 50000
#define N_EDGES 800000
#define HID     256
#define EMB     128
#define IN_F    10
#define BN_EPS  1e-5f

// ---------------- scratch (static device globals; no allocation) ------------
__device__ float g_bufA[N_NODES * HID];   // h (current activations)
__device__ float g_bufB[N_NODES * HID];   // agg (scatter target)
__device__ float g_bufC[N_NODES * HID];   // pre-BN GEMM output
__device__ float g_rcnt[N_NODES];         // 1/max(indegree,1)
__device__ float g_stats[2 * HID];        // [0:256) col sums, [256:512) col sumsq
__device__ float g_scale[HID];
__device__ float g_shift[HID];

// ---------------- small utility kernels ------------------------------------
__global__ void zero_f4(float4* p, int n4) {
    int i = blockIdx.x * blockDim.x + threadIdx.x;
    if (i < n4) p[i] = make_float4(0.f, 0.f, 0.f, 0.f);
}

__global__ void count_edges(const int* __restrict__ ei, float* __restrict__ cnt) {
    int e = blockIdx.x * blockDim.x + threadIdx.x;
    if (e < N_EDGES) atomicAdd(cnt + ei[N_EDGES + e], 1.0f);
}

__global__ void make_rcnt(float* __restrict__ cnt) {
    int i = blockIdx.x * blockDim.x + threadIdx.x;
    if (i < N_NODES) cnt[i] = 1.0f / fmaxf(cnt[i], 1.0f);
}

// ---------------- input projection: [50000,10] @ [10,256] + b --------------
__global__ __launch_bounds__(256) void input_proj(const float* __restrict__ x,
                                                  const float* __restrict__ w,
                                                  const float* __restrict__ b,
                                                  float* __restrict__ out) {
    __shared__ float ws[IN_F * HID];
    __shared__ float xs[16 * IN_F];
    int t = threadIdx.x;
    for (int i = t; i < IN_F * HID; i += 256) ws[i] = w[i];
    int r0 = blockIdx.x * 16;
    int nr = min(16, N_NODES - r0);
    for (int i = t; i < nr * IN_F; i += 256) xs[i] = x[(size_t)r0 * IN_F + i];
    __syncthreads();
    float bb = b[t];
    for (int r = 0; r < nr; r++) {
        float s = bb;
#pragma unroll
        for (int k = 0; k < IN_F; k++) s += xs[r * IN_F + k] * ws[k * HID + t];
        out[(size_t)(r0 + r) * HID + t] = s;
    }
}

// ---------------- BatchNorm (training-mode batch stats) --------------------
__global__ __launch_bounds__(256) void bn_stats(const float* __restrict__ h) {
    int c = threadIdx.x;
    float s = 0.f, s2 = 0.f;
    for (int r = blockIdx.x; r < N_NODES; r += gridDim.x) {
        float v = h[(size_t)r * HID + c];
        s += v; s2 += v * v;
    }
    atomicAdd(&g_stats[c], s);
    atomicAdd(&g_stats[HID + c], s2);
}

__global__ void bn_finalize(const float* __restrict__ g, const float* __restrict__ be) {
    int c = threadIdx.x;
    float mu  = g_stats[c] * (1.0f / N_NODES);
    float var = g_stats[HID + c] * (1.0f / N_NODES) - mu * mu;
    float sc  = g[c] * rsqrtf(var + BN_EPS);
    g_scale[c] = sc;
    g_shift[c] = be[c] - mu * sc;
}

__global__ void bn_relu(const float4* __restrict__ in, float4* __restrict__ out) {
    int i = blockIdx.x * blockDim.x + threadIdx.x;
    if (i >= N_NODES * HID / 4) return;
    int c = (i * 4) & (HID - 1);
    float4 v = in[i];
    v.x = fmaxf(v.x * g_scale[c + 0] + g_shift[c + 0], 0.f);
    v.y = fmaxf(v.y * g_scale[c + 1] + g_shift[c + 1], 0.f);
    v.z = fmaxf(v.z * g_scale[c + 2] + g_shift[c + 2], 0.f);
    v.w = fmaxf(v.w * g_scale[c + 3] + g_shift[c + 3], 0.f);
    out[i] = v;
}

// ---------------- edge aggregation: agg[dst] += h[src] ---------------------
// One warp per edge; 256 floats = 64 float4 = 32 lanes x 2 iterations.
// float4 gather (LDG.128) + scalar REDG.ADD.F32 scatter.
__global__ __launch_bounds__(256) void agg_edges(const int* __restrict__ ei,
                                                 const float* __restrict__ h,
                                                 float* __restrict__ agg) {
    int w = (blockIdx.x * blockDim.x + threadIdx.x) >> 5;
    int lane = threadIdx.x & 31;
    if (w >= N_EDGES) return;
    int src = __ldg(ei + w);
    int dst = __ldg(ei + N_EDGES + w);
    const float4* hr = (const float4*)(h + (size_t)src * HID);
    float* ar = agg + (size_t)dst * HID;
#pragma unroll
    for (int i = 0; i < 2; i++) {
        float4 v = hr[lane + 32 * i];
        int o = (lane + 32 * i) * 4;
        atomicAdd(ar + o + 0, v.x);
        atomicAdd(ar + o + 1, v.y);
        atomicAdd(ar + o + 2, v.z);
        atomicAdd(ar + o + 3, v.w);
    }
}

// ---------------- dual GEMM: C = (rs .* A1) @ W1 + A2 @ W2 + bias ----------
// M = N_NODES, K = 256 per phase, N in {256,128}. 64x64 tile, 256 threads,
// 4x4 per thread.
__global__ __launch_bounds__(256) void dual_gemm(const float* __restrict__ A1,
                                                 const float* __restrict__ rs,
                                                 const float* __restrict__ A2,
                                                 const float* __restrict__ W1,
                                                 const float* __restrict__ W2,
                                                 const float* __restrict__ bias,
                                                 float* __restrict__ C, int N) {
    __shared__ float As[64][17];
    __shared__ __align__(16) float Bs[16][64];

    int tid = threadIdx.x;
    int tx = tid & 15, ty = tid >> 4;
    int m0 = blockIdx.x * 64, n0 = blockIdx.y * 64;
    int lm = tid >> 2, lk = (tid & 3) * 4;   // A tile load: row lm, k off lk
    int bk = tid >> 4, bn = (tid & 15) * 4;  // B tile load: k row bk, n off bn

    float acc[4][4] = {};
    int grow = m0 + lm;
    bool rowok = grow < N_NODES;
    float rmul0 = rowok ? rs[grow] : 0.f;

#pragma unroll 1
    for (int phase = 0; phase < 2; phase++) {
        const float* A = phase ? A2 : A1;
        const float* W = phase ? W2 : W1;
        float rmul = phase ? 1.0f : rmul0;
#pragma unroll 1
        for (int k0 = 0; k0 < HID; k0 += 16) {
            float4 av = rowok ? *(const float4*)(A + (size_t)grow * HID + k0 + lk)
                              : make_float4(0.f, 0.f, 0.f, 0.f);
            float4 bv = *(const float4*)(W + (size_t)(k0 + bk) * N + n0 + bn);
            __syncthreads();
            As[lm][lk + 0] = av.x * rmul;
            As[lm][lk + 1] = av.y * rmul;
            As[lm][lk + 2] = av.z * rmul;
            As[lm][lk + 3] = av.w * rmul;
            *(float4*)&Bs[bk][bn] = bv;
            __syncthreads();
#pragma unroll
            for (int k = 0; k < 16; k++) {
                float a0 = As[ty * 4 + 0][k];
                float a1 = As[ty * 4 + 1][k];
                float a2 = As[ty * 4 + 2][k];
                float a3 = As[ty * 4 + 3][k];
                float4 b = *(const float4*)&Bs[k][tx * 4];
                acc[0][0] += a0 * b.x; acc[0][1] += a0 * b.y; acc[0][2] += a0 * b.z; acc[0][3] += a0 * b.w;
                acc[1][0] += a1 * b.x; acc[1][1] += a1 * b.y; acc[1][2] += a1 * b.z; acc[1][3] += a1 * b.w;
                acc[2][0] += a2 * b.x; acc[2][1] += a2 * b.y; acc[2][2] += a2 * b.z; acc[2][3] += a2 * b.w;
                acc[3][0] += a3 * b.x; acc[3][1] += a3 * b.y; acc[3][2] += a3 * b.z; acc[3][3] += a3 * b.w;
            }
        }
    }

    float4 bb = *(const float4*)(bias + n0 + tx * 4);
#pragma unroll
    for (int i = 0; i < 4; i++) {
        int m = m0 + ty * 4 + i;
        if (m < N_NODES) {
            float4 o;
            o.x = acc[i][0] + bb.x;
            o.y = acc[i][1] + bb.y;
            o.z = acc[i][2] + bb.z;
            o.w = acc[i][3] + bb.w;
            *(float4*)(C + (size_t)m * N + n0 + tx * 4) = o;
        }
    }
}

// ---------------- orchestration --------------------------------------------
extern "C" void kernel_launch(void* const* d_in, const int* in_sizes, int n_in,
                              void* d_out, int out_size) {
    const float* x    = (const float*)d_in[0];
    const int*   ei   = (const int*)d_in[1];    // int32 [2, E] (jax canonicalizes int64->int32)
    const float* w_in = (const float*)d_in[2];
    const float* b_in = (const float*)d_in[3];
    const float* gi   = (const float*)d_in[4];
    const float* bei  = (const float*)d_in[5];
    const float* wl1  = (const float*)d_in[6];
    const float* bl1  = (const float*)d_in[7];
    const float* wr1  = (const float*)d_in[8];
    const float* g1   = (const float*)d_in[9];
    const float* be1  = (const float*)d_in[10];
    const float* wl2  = (const float*)d_in[11];
    const float* bl2  = (const float*)d_in[12];
    const float* wr2  = (const float*)d_in[13];
    const float* g2   = (const float*)d_in[14];
    const float* be2  = (const float*)d_in[15];
    const float* wl3  = (const float*)d_in[16];
    const float* bl3  = (const float*)d_in[17];
    const float* wr3  = (const float*)d_in[18];
    float* out = (float*)d_out;

    float *bufA, *bufB, *bufC, *rcnt, *stats;
    cudaGetSymbolAddress((void**)&bufA, g_bufA);
    cudaGetSymbolAddress((void**)&bufB, g_bufB);
    cudaGetSymbolAddress((void**)&bufC, g_bufC);
    cudaGetSymbolAddress((void**)&rcnt, g_rcnt);
    cudaGetSymbolAddress((void**)&stats, g_stats);

    const int NB4 = N_NODES * HID / 4;  // 3.2M float4 per buffer

    // degree counts (shared across all three layers)
    zero_f4<<<(N_NODES / 4 + 255) / 256, 256>>>((float4*)rcnt, N_NODES / 4);
    count_edges<<<(N_EDGES + 255) / 256, 256>>>(ei, rcnt);
    make_rcnt<<<(N_NODES + 255) / 256, 256>>>(rcnt);

    // input projection + BN + ReLU -> bufA (h0)
    input_proj<<<(N_NODES + 15) / 16, 256>>>(x, w_in, b_in, bufC);
    zero_f4<<<1, 128>>>((float4*)stats, 2 * HID / 4);
    bn_stats<<<256, 256>>>(bufC);
    bn_finalize<<<1, HID>>>(gi, bei);
    bn_relu<<<(NB4 + 255) / 256, 256>>>((const float4*)bufC, (float4*)bufA);

    dim3 ggrid((N_NODES + 63) / 64, HID / 64);
    const int AGG_BLOCKS = (N_EDGES * 32) / 256;

    // ---- SAGE layer 1 ----
    zero_f4<<<(NB4 + 255) / 256, 256>>>((float4*)bufB, NB4);
    agg_edges<<<AGG_BLOCKS, 256>>>(ei, bufA, bufB);
    dual_gemm<<<ggrid, 256>>>(bufB, rcnt, bufA, wl1, wr1, bl1, bufC, HID);
    zero_f4<<<1, 128>>>((float4*)stats, 2 * HID / 4);
    bn_stats<<<256, 256>>>(bufC);
    bn_finalize<<<1, HID>>>(g1, be1);
    bn_relu<<<(NB4 + 255) / 256, 256>>>((const float4*)bufC, (float4*)bufA);

    // ---- SAGE layer 2 ----
    zero_f4<<<(NB4 + 255) / 256, 256>>>((float4*)bufB, NB4);
    agg_edges<<<AGG_BLOCKS, 256>>>(ei, bufA, bufB);
    dual_gemm<<<ggrid, 256>>>(bufB, rcnt, bufA, wl2, wr2, bl2, bufC, HID);
    zero_f4<<<1, 128>>>((float4*)stats, 2 * HID / 4);
    bn_stats<<<256, 256>>>(bufC);
    bn_finalize<<<1, HID>>>(g2, be2);
    bn_relu<<<(NB4 + 255) / 256, 256>>>((const float4*)bufC, (float4*)bufA);

    // ---- SAGE layer 3 (256 -> 128, no BN/ReLU) -> d_out ----
    zero_f4<<<(NB4 + 255) / 256, 256>>>((float4*)bufB, NB4);
    agg_edges<<<AGG_BLOCKS, 256>>>(ei, bufA, bufB);
    dim3 ogrid((N_NODES + 63) / 64, EMB / 64);
    dual_gemm<<<ogrid, 256>>>(bufB, rcnt, bufA, wl3, wr3, bl3, out, EMB);
}

// round 4
// speedup vs baseline: 1.5786x; 1.5786x over previous
#include <cuda_runtime.h>

#define N_NODES 50000
#define N_EDGES 800000
#define HID     256
#define EMB     128
#define IN_F    10
#define BN_EPS  1e-5f

// ---------------- scratch (static device globals; no allocation) ------------
__device__ float g_bufA[N_NODES * HID];   // h (current activations)
__device__ float g_bufB[N_NODES * HID];   // agg (gather target)
__device__ float g_bufC[N_NODES * HID];   // pre-BN GEMM output
__device__ float g_rcnt[N_NODES];         // 1/max(indegree,1)
__device__ int   g_deg[N_NODES];
__device__ int   g_rowstart[N_NODES + 1];
__device__ int   g_cursor[N_NODES];
__device__ int   g_csrsrc[N_EDGES];
__device__ float g_stats[2 * HID];        // col sums / col sumsq
__device__ float g_scale[HID];
__device__ float g_shift[HID];

// ---------------- CSR construction -----------------------------------------
__global__ void zero_int(int* p, int n) {
    int i = blockIdx.x * blockDim.x + threadIdx.x;
    if (i < n) p[i] = 0;
}

__global__ void count_deg(const int* __restrict__ ei, int* __restrict__ deg) {
    int e = blockIdx.x * blockDim.x + threadIdx.x;
    if (e < N_EDGES) atomicAdd(deg + ei[N_EDGES + e], 1);
}

// single-block exclusive scan of degrees -> rowstart, cursor, rcnt
__global__ __launch_bounds__(1024) void scan_deg(const int* __restrict__ deg,
                                                 int* __restrict__ rowstart,
                                                 int* __restrict__ cursor,
                                                 float* __restrict__ rcnt) {
    __shared__ int partial[1024];
    const int CH = (N_NODES + 1023) / 1024;  // 49
    int t = threadIdx.x;
    int base = t * CH;
    int s = 0;
    for (int i = 0; i < CH; i++) {
        int idx = base + i;
        if (idx < N_NODES) s += deg[idx];
    }
    partial[t] = s;
    __syncthreads();
    for (int off = 1; off < 1024; off <<= 1) {
        int v = (t >= off) ? partial[t - off] : 0;
        __syncthreads();
        partial[t] += v;
        __syncthreads();
    }
    int run = (t == 0) ? 0 : partial[t - 1];
    for (int i = 0; i < CH; i++) {
        int idx = base + i;
        if (idx < N_NODES) {
            rowstart[idx] = run;
            cursor[idx] = run;
            rcnt[idx] = 1.0f / fmaxf((float)deg[idx], 1.0f);
            run += deg[idx];
        }
    }
    if (t == 1023) rowstart[N_NODES] = run;
}

__global__ void fill_csr(const int* __restrict__ ei, int* __restrict__ cursor,
                         int* __restrict__ csrsrc) {
    int e = blockIdx.x * blockDim.x + threadIdx.x;
    if (e < N_EDGES) {
        int dst = ei[N_EDGES + e];
        int p = atomicAdd(cursor + dst, 1);
        csrsrc[p] = ei[e];
    }
}

// ---------------- input projection: [50000,10] @ [10,256] + b --------------
__global__ __launch_bounds__(256) void input_proj(const float* __restrict__ x,
                                                  const float* __restrict__ w,
                                                  const float* __restrict__ b,
                                                  float* __restrict__ out) {
    __shared__ float ws[IN_F * HID];
    __shared__ float xs[16 * IN_F];
    int t = threadIdx.x;
    for (int i = t; i < IN_F * HID; i += 256) ws[i] = w[i];
    int r0 = blockIdx.x * 16;
    int nr = min(16, N_NODES - r0);
    for (int i = t; i < nr * IN_F; i += 256) xs[i] = x[(size_t)r0 * IN_F + i];
    __syncthreads();
    float bb = b[t];
    for (int r = 0; r < nr; r++) {
        float s = bb;
#pragma unroll
        for (int k = 0; k < IN_F; k++) s += xs[r * IN_F + k] * ws[k * HID + t];
        out[(size_t)(r0 + r) * HID + t] = s;
    }
}

// ---------------- BatchNorm (training-mode batch stats) --------------------
__global__ void zero_stats() {
    g_stats[threadIdx.x] = 0.f;
    g_stats[HID + threadIdx.x] = 0.f;
}

__global__ __launch_bounds__(256) void bn_stats(const float* __restrict__ h) {
    int c = threadIdx.x;
    float s = 0.f, s2 = 0.f;
    for (int r = blockIdx.x; r < N_NODES; r += gridDim.x) {
        float v = h[(size_t)r * HID + c];
        s += v; s2 += v * v;
    }
    atomicAdd(&g_stats[c], s);
    atomicAdd(&g_stats[HID + c], s2);
}

__global__ void bn_finalize(const float* __restrict__ g, const float* __restrict__ be) {
    int c = threadIdx.x;
    float mu  = g_stats[c] * (1.0f / N_NODES);
    float var = g_stats[HID + c] * (1.0f / N_NODES) - mu * mu;
    float sc  = g[c] * rsqrtf(var + BN_EPS);
    g_scale[c] = sc;
    g_shift[c] = be[c] - mu * sc;
}

__global__ void bn_relu(const float4* __restrict__ in, float4* __restrict__ out) {
    int i = blockIdx.x * blockDim.x + threadIdx.x;
    if (i >= N_NODES * HID / 4) return;
    int c = (i * 4) & (HID - 1);
    float4 v = in[i];
    v.x = fmaxf(v.x * g_scale[c + 0] + g_shift[c + 0], 0.f);
    v.y = fmaxf(v.y * g_scale[c + 1] + g_shift[c + 1], 0.f);
    v.z = fmaxf(v.z * g_scale[c + 2] + g_shift[c + 2], 0.f);
    v.w = fmaxf(v.w * g_scale[c + 3] + g_shift[c + 3], 0.f);
    out[i] = v;
}

// ---------------- aggregation: gather-mean over CSR ------------------------
// One block per node, one thread per feature column; mean folded in.
__global__ __launch_bounds__(256) void agg_gather(const int* __restrict__ rowstart,
                                                  const int* __restrict__ csrsrc,
                                                  const float* __restrict__ rcnt,
                                                  const float* __restrict__ h,
                                                  float* __restrict__ agg) {
    int node = blockIdx.x;
    int c = threadIdx.x;
    int j = rowstart[node];
    int e = rowstart[node + 1];
    float acc = 0.f;
    for (; j + 4 <= e; j += 4) {
        int s0 = __ldg(csrsrc + j + 0);
        int s1 = __ldg(csrsrc + j + 1);
        int s2 = __ldg(csrsrc + j + 2);
        int s3 = __ldg(csrsrc + j + 3);
        float v0 = __ldg(h + (size_t)s0 * HID + c);
        float v1 = __ldg(h + (size_t)s1 * HID + c);
        float v2 = __ldg(h + (size_t)s2 * HID + c);
        float v3 = __ldg(h + (size_t)s3 * HID + c);
        acc += v0 + v1 + v2 + v3;
    }
    for (; j < e; j++)
        acc += __ldg(h + (size_t)__ldg(csrsrc + j) * HID + c);
    agg[(size_t)node * HID + c] = acc * rcnt[node];
}

// ---------------- dual GEMM: C = A1 @ W1 + A2 @ W2 + bias ------------------
// 128x128 tile, 256 threads, 8x8 per thread, K-chunk 8.
__global__ __launch_bounds__(256, 2) void dual_gemm(const float* __restrict__ A1,
                                                    const float* __restrict__ A2,
                                                    const float* __restrict__ W1,
                                                    const float* __restrict__ W2,
                                                    const float* __restrict__ bias,
                                                    float* __restrict__ C, int N) {
    __shared__ float As[8][132];   // [k][row], padded
    __shared__ __align__(16) float Bs[8][128];  // [k][col]

    int tid = threadIdx.x;
    int tx = tid & 15, ty = tid >> 4;
    int m0 = blockIdx.x * 128, n0 = blockIdx.y * 128;

    int ar = tid >> 1;          // A load: row 0..127
    int ak = (tid & 1) * 4;     // A load: k offset 0 or 4
    int br = tid >> 5;          // B load: k row 0..7
    int bc = (tid & 31) * 4;    // B load: col offset

    float acc[8][8] = {};
    int grow = m0 + ar;
    bool rowok = grow < N_NODES;

#pragma unroll 1
    for (int phase = 0; phase < 2; phase++) {
        const float* A = phase ? A2 : A1;
        const float* W = phase ? W2 : W1;
#pragma unroll 1
        for (int k0 = 0; k0 < HID; k0 += 8) {
            float4 av = rowok ? *(const float4*)(A + (size_t)grow * HID + k0 + ak)
                              : make_float4(0.f, 0.f, 0.f, 0.f);
            float4 bv = *(const float4*)(W + (size_t)(k0 + br) * N + n0 + bc);
            __syncthreads();
            As[ak + 0][ar] = av.x;
            As[ak + 1][ar] = av.y;
            As[ak + 2][ar] = av.z;
            As[ak + 3][ar] = av.w;
            *(float4*)&Bs[br][bc] = bv;
            __syncthreads();
#pragma unroll
            for (int k = 0; k < 8; k++) {
                float4 a0 = *(const float4*)&As[k][ty * 8];
                float4 a1 = *(const float4*)&As[k][ty * 8 + 4];
                float4 b0 = *(const float4*)&Bs[k][tx * 8];
                float4 b1 = *(const float4*)&Bs[k][tx * 8 + 4];
                float a[8] = {a0.x, a0.y, a0.z, a0.w, a1.x, a1.y, a1.z, a1.w};
                float b[8] = {b0.x, b0.y, b0.z, b0.w, b1.x, b1.y, b1.z, b1.w};
#pragma unroll
                for (int i = 0; i < 8; i++)
#pragma unroll
                    for (int jj = 0; jj < 8; jj++)
                        acc[i][jj] += a[i] * b[jj];
            }
        }
    }

    float4 bb0 = *(const float4*)(bias + n0 + tx * 8);
    float4 bb1 = *(const float4*)(bias + n0 + tx * 8 + 4);
    float bbv[8] = {bb0.x, bb0.y, bb0.z, bb0.w, bb1.x, bb1.y, bb1.z, bb1.w};
#pragma unroll
    for (int i = 0; i < 8; i++) {
        int m = m0 + ty * 8 + i;
        if (m < N_NODES) {
            float4 o0, o1;
            o0.x = acc[i][0] + bbv[0]; o0.y = acc[i][1] + bbv[1];
            o0.z = acc[i][2] + bbv[2]; o0.w = acc[i][3] + bbv[3];
            o1.x = acc[i][4] + bbv[4]; o1.y = acc[i][5] + bbv[5];
            o1.z = acc[i][6] + bbv[6]; o1.w = acc[i][7] + bbv[7];
            *(float4*)(C + (size_t)m * N + n0 + tx * 8) = o0;
            *(float4*)(C + (size_t)m * N + n0 + tx * 8 + 4) = o1;
        }
    }
}

// ---------------- orchestration --------------------------------------------
extern "C" void kernel_launch(void* const* d_in, const int* in_sizes, int n_in,
                              void* d_out, int out_size) {
    const float* x    = (const float*)d_in[0];
    const int*   ei   = (const int*)d_in[1];    // int32 [2, E]
    const float* w_in = (const float*)d_in[2];
    const float* b_in = (const float*)d_in[3];
    const float* gi   = (const float*)d_in[4];
    const float* bei  = (const float*)d_in[5];
    const float* wl1  = (const float*)d_in[6];
    const float* bl1  = (const float*)d_in[7];
    const float* wr1  = (const float*)d_in[8];
    const float* g1   = (const float*)d_in[9];
    const float* be1  = (const float*)d_in[10];
    const float* wl2  = (const float*)d_in[11];
    const float* bl2  = (const float*)d_in[12];
    const float* wr2  = (const float*)d_in[13];
    const float* g2   = (const float*)d_in[14];
    const float* be2  = (const float*)d_in[15];
    const float* wl3  = (const float*)d_in[16];
    const float* bl3  = (const float*)d_in[17];
    const float* wr3  = (const float*)d_in[18];
    float* out = (float*)d_out;

    float *bufA, *bufB, *bufC, *rcnt;
    int *deg, *rowstart, *cursor, *csrsrc;
    cudaGetSymbolAddress((void**)&bufA, g_bufA);
    cudaGetSymbolAddress((void**)&bufB, g_bufB);
    cudaGetSymbolAddress((void**)&bufC, g_bufC);
    cudaGetSymbolAddress((void**)&rcnt, g_rcnt);
    cudaGetSymbolAddress((void**)&deg, g_deg);
    cudaGetSymbolAddress((void**)&rowstart, g_rowstart);
    cudaGetSymbolAddress((void**)&cursor, g_cursor);
    cudaGetSymbolAddress((void**)&csrsrc, g_csrsrc);

    const int NB4 = N_NODES * HID / 4;

    // ---- CSR build (once) ----
    zero_int<<<(N_NODES + 255) / 256, 256>>>(deg, N_NODES);
    count_deg<<<(N_EDGES + 255) / 256, 256>>>(ei, deg);
    scan_deg<<<1, 1024>>>(deg, rowstart, cursor, rcnt);
    fill_csr<<<(N_EDGES + 255) / 256, 256>>>(ei, cursor, csrsrc);

    // ---- input projection + BN + ReLU -> bufA (h0) ----
    input_proj<<<(N_NODES + 15) / 16, 256>>>(x, w_in, b_in, bufC);
    zero_stats<<<1, HID>>>();
    bn_stats<<<256, 256>>>(bufC);
    bn_finalize<<<1, HID>>>(gi, bei);
    bn_relu<<<(NB4 + 255) / 256, 256>>>((const float4*)bufC, (float4*)bufA);

    dim3 ggrid((N_NODES + 127) / 128, HID / 128);

    // ---- SAGE layer 1 ----
    agg_gather<<<N_NODES, 256>>>(rowstart, csrsrc, rcnt, bufA, bufB);
    dual_gemm<<<ggrid, 256>>>(bufB, bufA, wl1, wr1, bl1, bufC, HID);
    zero_stats<<<1, HID>>>();
    bn_stats<<<256, 256>>>(bufC);
    bn_finalize<<<1, HID>>>(g1, be1);
    bn_relu<<<(NB4 + 255) / 256, 256>>>((const float4*)bufC, (float4*)bufA);

    // ---- SAGE layer 2 ----
    agg_gather<<<N_NODES, 256>>>(rowstart, csrsrc, rcnt, bufA, bufB);
    dual_gemm<<<ggrid, 256>>>(bufB, bufA, wl2, wr2, bl2, bufC, HID);
    zero_stats<<<1, HID>>>();
    bn_stats<<<256, 256>>>(bufC);
    bn_finalize<<<1, HID>>>(g2, be2);
    bn_relu<<<(NB4 + 255) / 256, 256>>>((const float4*)bufC, (float4*)bufA);

    // ---- SAGE layer 3 (256 -> 128, no BN/ReLU) -> d_out ----
    agg_gather<<<N_NODES, 256>>>(rowstart, csrsrc, rcnt, bufA, bufB);
    dim3 ogrid((N_NODES + 127) / 128, EMB / 128);
    dual_gemm<<<ogrid, 256>>>(bufB, bufA, wl3, wr3, bl3, out, EMB);
}

// round 6
// speedup vs baseline: 2.2371x; 1.4171x over previous
#include <cuda_runtime.h>
#include <cstdint>

#define N_NODES 50000
#define N_EDGES 800000
#define HID     256
#define EMB     128
#define IN_F    10
#define BN_EPS  1e-5f

// ---------------- scratch (static device globals; no allocation) ------------
__device__ float g_bufA[N_NODES * HID];   // h (current activations)
__device__ float g_bufB[N_NODES * HID];   // agg (gather target)
__device__ float g_bufC[N_NODES * HID];   // pre-BN GEMM output
__device__ float g_rcnt[N_NODES];
__device__ int   g_deg[N_NODES];
__device__ int   g_rowstart[N_NODES + 1];
__device__ int   g_cursor[N_NODES];
__device__ int   g_csrsrc[N_EDGES];
__device__ float g_stats[2 * HID];
__device__ float g_scale[HID];
__device__ float g_shift[HID];

__device__ __forceinline__ float to_tf32(float x) {
    float y;
    asm("cvt.rna.tf32.f32 %0, %1;" : "=f"(y) : "f"(x));
    return y;
}

// ---------------- CSR construction -----------------------------------------
__global__ void zero_int(int* p, int n) {
    int i = blockIdx.x * blockDim.x + threadIdx.x;
    if (i < n) p[i] = 0;
}

__global__ void count_deg(const int* __restrict__ ei, int* __restrict__ deg) {
    int e = blockIdx.x * blockDim.x + threadIdx.x;
    if (e < N_EDGES) atomicAdd(deg + ei[N_EDGES + e], 1);
}

__global__ __launch_bounds__(1024) void scan_deg(const int* __restrict__ deg,
                                                 int* __restrict__ rowstart,
                                                 int* __restrict__ cursor,
                                                 float* __restrict__ rcnt) {
    __shared__ int partial[1024];
    const int CH = (N_NODES + 1023) / 1024;
    int t = threadIdx.x;
    int base = t * CH;
    int s = 0;
    for (int i = 0; i < CH; i++) {
        int idx = base + i;
        if (idx < N_NODES) s += deg[idx];
    }
    partial[t] = s;
    __syncthreads();
    for (int off = 1; off < 1024; off <<= 1) {
        int v = (t >= off) ? partial[t - off] : 0;
        __syncthreads();
        partial[t] += v;
        __syncthreads();
    }
    int run = (t == 0) ? 0 : partial[t - 1];
    for (int i = 0; i < CH; i++) {
        int idx = base + i;
        if (idx < N_NODES) {
            rowstart[idx] = run;
            cursor[idx] = run;
            rcnt[idx] = 1.0f / fmaxf((float)deg[idx], 1.0f);
            run += deg[idx];
        }
    }
    if (t == 1023) rowstart[N_NODES] = run;
}

__global__ void fill_csr(const int* __restrict__ ei, int* __restrict__ cursor,
                         int* __restrict__ csrsrc) {
    int e = blockIdx.x * blockDim.x + threadIdx.x;
    if (e < N_EDGES) {
        int dst = ei[N_EDGES + e];
        int p = atomicAdd(cursor + dst, 1);
        csrsrc[p] = ei[e];
    }
}

// ---------------- input projection ------------------------------------------
__global__ __launch_bounds__(256) void input_proj(const float* __restrict__ x,
                                                  const float* __restrict__ w,
                                                  const float* __restrict__ b,
                                                  float* __restrict__ out) {
    __shared__ float ws[IN_F * HID];
    __shared__ float xs[16 * IN_F];
    int t = threadIdx.x;
    for (int i = t; i < IN_F * HID; i += 256) ws[i] = w[i];
    int r0 = blockIdx.x * 16;
    int nr = min(16, N_NODES - r0);
    for (int i = t; i < nr * IN_F; i += 256) xs[i] = x[(size_t)r0 * IN_F + i];
    __syncthreads();
    float bb = b[t];
    for (int r = 0; r < nr; r++) {
        float s = bb;
#pragma unroll
        for (int k = 0; k < IN_F; k++) s += xs[r * IN_F + k] * ws[k * HID + t];
        out[(size_t)(r0 + r) * HID + t] = s;
    }
}

// ---------------- BatchNorm --------------------------------------------------
__global__ void zero_stats() {
    g_stats[threadIdx.x] = 0.f;
    g_stats[HID + threadIdx.x] = 0.f;
}

__global__ __launch_bounds__(256) void bn_stats(const float* __restrict__ h) {
    int c = threadIdx.x;
    float s = 0.f, s2 = 0.f;
    for (int r = blockIdx.x; r < N_NODES; r += gridDim.x) {
        float v = h[(size_t)r * HID + c];
        s += v; s2 += v * v;
    }
    atomicAdd(&g_stats[c], s);
    atomicAdd(&g_stats[HID + c], s2);
}

__global__ void bn_finalize(const float* __restrict__ g, const float* __restrict__ be) {
    int c = threadIdx.x;
    float mu  = g_stats[c] * (1.0f / N_NODES);
    float var = g_stats[HID + c] * (1.0f / N_NODES) - mu * mu;
    float sc  = g[c] * rsqrtf(var + BN_EPS);
    g_scale[c] = sc;
    g_shift[c] = be[c] - mu * sc;
}

__global__ void bn_relu(const float4* __restrict__ in, float4* __restrict__ out) {
    int i = blockIdx.x * blockDim.x + threadIdx.x;
    if (i >= N_NODES * HID / 4) return;
    int c = (i * 4) & (HID - 1);
    float4 v = in[i];
    v.x = fmaxf(v.x * g_scale[c + 0] + g_shift[c + 0], 0.f);
    v.y = fmaxf(v.y * g_scale[c + 1] + g_shift[c + 1], 0.f);
    v.z = fmaxf(v.z * g_scale[c + 2] + g_shift[c + 2], 0.f);
    v.w = fmaxf(v.w * g_scale[c + 3] + g_shift[c + 3], 0.f);
    out[i] = v;
}

// ---------------- aggregation: gather-mean over CSR --------------------------
__global__ __launch_bounds__(256) void agg_gather(const int* __restrict__ rowstart,
                                                  const int* __restrict__ csrsrc,
                                                  const float* __restrict__ rcnt,
                                                  const float* __restrict__ h,
                                                  float* __restrict__ agg) {
    int node = blockIdx.x;
    int c = threadIdx.x;
    int j = rowstart[node];
    int e = rowstart[node + 1];
    float acc = 0.f;
    for (; j + 4 <= e; j += 4) {
        int s0 = __ldg(csrsrc + j + 0);
        int s1 = __ldg(csrsrc + j + 1);
        int s2 = __ldg(csrsrc + j + 2);
        int s3 = __ldg(csrsrc + j + 3);
        acc += __ldg(h + (size_t)s0 * HID + c) + __ldg(h + (size_t)s1 * HID + c)
             + __ldg(h + (size_t)s2 * HID + c) + __ldg(h + (size_t)s3 * HID + c);
    }
    for (; j < e; j++)
        acc += __ldg(h + (size_t)__ldg(csrsrc + j) * HID + c);
    agg[(size_t)node * HID + c] = acc * rcnt[node];
}

// ---------------- TF32 mma.sync dual GEMM ------------------------------------
// C[m0:m0+128, n0:n0+128] = A1 @ W1 + A2 @ W2 + bias.  K = 256 per phase.
// 8 warps in 2(m) x 4(n); warp tile 64x32; mma.m16n8k8 tf32; K-chunk 16,
// double-buffered smem.
__device__ __forceinline__ void mma8(float* c, const uint32_t* a, const uint32_t* b) {
    asm volatile(
        "mma.sync.aligned.m16n8k8.row.col.f32.tf32.tf32.f32 "
        "{%0,%1,%2,%3}, {%4,%5,%6,%7}, {%8,%9}, {%0,%1,%2,%3};"
        : "+f"(c[0]), "+f"(c[1]), "+f"(c[2]), "+f"(c[3])
        : "r"(a[0]), "r"(a[1]), "r"(a[2]), "r"(a[3]), "r"(b[0]), "r"(b[1]));
}

__global__ __launch_bounds__(256, 2) void mma_dual_gemm(
    const float* __restrict__ A1, const float* __restrict__ A2,
    const float* __restrict__ W1, const float* __restrict__ W2,
    const float* __restrict__ bias, float* __restrict__ C, int N) {
    __shared__ float As[2][16][132];   // [buf][k][m]
    __shared__ float Bs[2][16][132];   // [buf][k][n]

    int tid = threadIdx.x;
    int lane = tid & 31, wid = tid >> 5;
    int g = lane >> 2, tig = lane & 3;
    int wm = (wid & 1) * 64, wn = (wid >> 1) * 32;
    int m0 = blockIdx.x * 128, n0 = blockIdx.y * 128;

    // load indices (2 float4 per thread per tile)
    int ar0 = tid >> 1;                 // A rows: tid*2 elements -> r = tid/2? see below
    // A tile: 128 rows x 16 k = 512 float4. idx q*256+tid: r=idx>>2, c=(idx&3)*4
    // B tile: 16 k x 128 n = 512 float4. idx: kr=idx>>5, nc=(idx&31)*4
    (void)ar0;

    float acc[4][4][4] = {};
    float4 sa[2], sb[2];

#pragma unroll 1
    for (int i = 0; i < 33; i++) {
        // ---- global load for chunk i (skipped on last iteration) ----
        if (i < 32) {
            int ph = i >> 4;
            int k0 = (i & 15) * 16;
            const float* A = ph ? A2 : A1;
            const float* W = ph ? W2 : W1;
#pragma unroll
            for (int q = 0; q < 2; q++) {
                int idx = q * 256 + tid;
                int r = idx >> 2, c4 = (idx & 3) * 4;
                int m = m0 + r;
                sa[q] = (m < N_NODES) ? *(const float4*)(A + (size_t)m * HID + k0 + c4)
                                      : make_float4(0.f, 0.f, 0.f, 0.f);
                int kr = idx >> 5, nc = (idx & 31) * 4;
                sb[q] = *(const float4*)(W + (size_t)(k0 + kr) * N + n0 + nc);
            }
        }
        // ---- compute on chunk i-1 ----
        if (i > 0) {
            int buf = (i - 1) & 1;
#pragma unroll
            for (int ks = 0; ks < 2; ks++) {
                int kb = ks * 8;
                uint32_t af[4][4];
#pragma unroll
                for (int mi = 0; mi < 4; mi++) {
                    int m = wm + mi * 16 + g;
                    af[mi][0] = __float_as_uint(As[buf][kb + tig][m]);
                    af[mi][1] = __float_as_uint(As[buf][kb + tig][m + 8]);
                    af[mi][2] = __float_as_uint(As[buf][kb + tig + 4][m]);
                    af[mi][3] = __float_as_uint(As[buf][kb + tig + 4][m + 8]);
                }
                uint32_t bf[4][2];
#pragma unroll
                for (int ni = 0; ni < 4; ni++) {
                    int n = wn + ni * 8 + g;
                    bf[ni][0] = __float_as_uint(Bs[buf][kb + tig][n]);
                    bf[ni][1] = __float_as_uint(Bs[buf][kb + tig + 4][n]);
                }
#pragma unroll
                for (int mi = 0; mi < 4; mi++)
#pragma unroll
                    for (int ni = 0; ni < 4; ni++)
                        mma8(acc[mi][ni], af[mi], bf[ni]);
            }
        }
        // ---- store chunk i into smem ----
        if (i < 32) {
            int buf = i & 1;
            if (i > 0) __syncthreads();   // prior compute on this buf must finish
#pragma unroll
            for (int q = 0; q < 2; q++) {
                int idx = q * 256 + tid;
                int r = idx >> 2, c4 = (idx & 3) * 4;
                As[buf][c4 + 0][r] = to_tf32(sa[q].x);
                As[buf][c4 + 1][r] = to_tf32(sa[q].y);
                As[buf][c4 + 2][r] = to_tf32(sa[q].z);
                As[buf][c4 + 3][r] = to_tf32(sa[q].w);
                int kr = idx >> 5, nc = (idx & 31) * 4;
                float4 v;
                v.x = to_tf32(sb[q].x); v.y = to_tf32(sb[q].y);
                v.z = to_tf32(sb[q].z); v.w = to_tf32(sb[q].w);
                *(float4*)&Bs[buf][kr][nc] = v;
            }
            __syncthreads();
        }
    }

    // ---- epilogue: add bias, store ----
#pragma unroll
    for (int mi = 0; mi < 4; mi++) {
#pragma unroll
        for (int ni = 0; ni < 4; ni++) {
            int col = n0 + wn + ni * 8 + tig * 2;
            float b0 = bias[col], b1 = bias[col + 1];
            int row0 = m0 + wm + mi * 16 + g;
            int row1 = row0 + 8;
            if (row0 < N_NODES) {
                float2 o = make_float2(acc[mi][ni][0] + b0, acc[mi][ni][1] + b1);
                *(float2*)(C + (size_t)row0 * N + col) = o;
            }
            if (row1 < N_NODES) {
                float2 o = make_float2(acc[mi][ni][2] + b0, acc[mi][ni][3] + b1);
                *(float2*)(C + (size_t)row1 * N + col) = o;
            }
        }
    }
}

// ---------------- orchestration ----------------------------------------------
extern "C" void kernel_launch(void* const* d_in, const int* in_sizes, int n_in,
                              void* d_out, int out_size) {
    const float* x    = (const float*)d_in[0];
    const int*   ei   = (const int*)d_in[1];
    const float* w_in = (const float*)d_in[2];
    const float* b_in = (const float*)d_in[3];
    const float* gi   = (const float*)d_in[4];
    const float* bei  = (const float*)d_in[5];
    const float* wl1  = (const float*)d_in[6];
    const float* bl1  = (const float*)d_in[7];
    const float* wr1  = (const float*)d_in[8];
    const float* g1   = (const float*)d_in[9];
    const float* be1  = (const float*)d_in[10];
    const float* wl2  = (const float*)d_in[11];
    const float* bl2  = (const float*)d_in[12];
    const float* wr2  = (const float*)d_in[13];
    const float* g2   = (const float*)d_in[14];
    const float* be2  = (const float*)d_in[15];
    const float* wl3  = (const float*)d_in[16];
    const float* bl3  = (const float*)d_in[17];
    const float* wr3  = (const float*)d_in[18];
    float* out = (float*)d_out;

    float *bufA, *bufB, *bufC, *rcnt;
    int *deg, *rowstart, *cursor, *csrsrc;
    cudaGetSymbolAddress((void**)&bufA, g_bufA);
    cudaGetSymbolAddress((void**)&bufB, g_bufB);
    cudaGetSymbolAddress((void**)&bufC, g_bufC);
    cudaGetSymbolAddress((void**)&rcnt, g_rcnt);
    cudaGetSymbolAddress((void**)&deg, g_deg);
    cudaGetSymbolAddress((void**)&rowstart, g_rowstart);
    cudaGetSymbolAddress((void**)&cursor, g_cursor);
    cudaGetSymbolAddress((void**)&csrsrc, g_csrsrc);

    const int NB4 = N_NODES * HID / 4;

    // ---- CSR build ----
    zero_int<<<(N_NODES + 255) / 256, 256>>>(deg, N_NODES);
    count_deg<<<(N_EDGES + 255) / 256, 256>>>(ei, deg);
    scan_deg<<<1, 1024>>>(deg, rowstart, cursor, rcnt);
    fill_csr<<<(N_EDGES + 255) / 256, 256>>>(ei, cursor, csrsrc);

    // ---- input projection + BN + ReLU -> bufA ----
    input_proj<<<(N_NODES + 15) / 16, 256>>>(x, w_in, b_in, bufC);
    zero_stats<<<1, HID>>>();
    bn_stats<<<256, 256>>>(bufC);
    bn_finalize<<<1, HID>>>(gi, bei);
    bn_relu<<<(NB4 + 255) / 256, 256>>>((const float4*)bufC, (float4*)bufA);

    const int MB = (N_NODES + 127) / 128;  // 391
    dim3 ggrid(MB, HID / 128);             // 391 x 2
    dim3 ogrid(MB, EMB / 128);             // 391 x 1

    // ---- SAGE layer 1 ----
    agg_gather<<<N_NODES, 256>>>(rowstart, csrsrc, rcnt, bufA, bufB);
    mma_dual_gemm<<<ggrid, 256>>>(bufB, bufA, wl1, wr1, bl1, bufC, HID);
    zero_stats<<<1, HID>>>();
    bn_stats<<<256, 256>>>(bufC);
    bn_finalize<<<1, HID>>>(g1, be1);
    bn_relu<<<(NB4 + 255) / 256, 256>>>((const float4*)bufC, (float4*)bufA);

    // ---- SAGE layer 2 ----
    agg_gather<<<N_NODES, 256>>>(rowstart, csrsrc, rcnt, bufA, bufB);
    mma_dual_gemm<<<ggrid, 256>>>(bufB, bufA, wl2, wr2, bl2, bufC, HID);
    zero_stats<<<1, HID>>>();
    bn_stats<<<256, 256>>>(bufC);
    bn_finalize<<<1, HID>>>(g2, be2);
    bn_relu<<<(NB4 + 255) / 256, 256>>>((const float4*)bufC, (float4*)bufA);

    // ---- SAGE layer 3 (256 -> 128, no BN/ReLU) -> d_out ----
    agg_gather<<<N_NODES, 256>>>(rowstart, csrsrc, rcnt, bufA, bufB);
    mma_dual_gemm<<<ogrid, 256>>>(bufB, bufA, wl3, wr3, bl3, out, EMB);
}

// round 7
// speedup vs baseline: 2.7317x; 1.2211x over previous
#include <cuda_runtime.h>
#include <cstdint>

#define N_NODES 50000
#define N_EDGES 800000
#define HID     256
#define EMB     128
#define IN_F    10
#define BN_EPS  1e-5f

// ---------------- scratch (static device globals; no allocation) ------------
__device__ float g_bufA[N_NODES * HID];
__device__ float g_bufB[N_NODES * HID];   // agg (gather target)
__device__ float g_bufC[N_NODES * HID];
__device__ float g_rcnt[N_NODES];
__device__ int   g_deg[N_NODES];
__device__ int   g_rowstart[N_NODES + 1];
__device__ int   g_cursor[N_NODES];
__device__ int   g_csrsrc[N_EDGES];
__device__ float g_stats[2 * HID];
__device__ float g_scale[HID];
__device__ float g_shift[HID];

__device__ __forceinline__ float to_tf32(float x) {
    float y;
    asm("cvt.rna.tf32.f32 %0, %1;" : "=f"(y) : "f"(x));
    return y;
}

// ---------------- CSR construction -----------------------------------------
__global__ void zero_int(int* p, int n) {
    int i = blockIdx.x * blockDim.x + threadIdx.x;
    if (i < n) p[i] = 0;
}

__global__ void count_deg(const int* __restrict__ ei, int* __restrict__ deg) {
    int e = blockIdx.x * blockDim.x + threadIdx.x;
    if (e < N_EDGES) atomicAdd(deg + ei[N_EDGES + e], 1);
}

__global__ __launch_bounds__(1024) void scan_deg(const int* __restrict__ deg,
                                                 int* __restrict__ rowstart,
                                                 int* __restrict__ cursor,
                                                 float* __restrict__ rcnt) {
    __shared__ int partial[1024];
    const int CH = (N_NODES + 1023) / 1024;
    int t = threadIdx.x;
    int base = t * CH;
    int s = 0;
    for (int i = 0; i < CH; i++) {
        int idx = base + i;
        if (idx < N_NODES) s += deg[idx];
    }
    partial[t] = s;
    __syncthreads();
    for (int off = 1; off < 1024; off <<= 1) {
        int v = (t >= off) ? partial[t - off] : 0;
        __syncthreads();
        partial[t] += v;
        __syncthreads();
    }
    int run = (t == 0) ? 0 : partial[t - 1];
    for (int i = 0; i < CH; i++) {
        int idx = base + i;
        if (idx < N_NODES) {
            rowstart[idx] = run;
            cursor[idx] = run;
            rcnt[idx] = 1.0f / fmaxf((float)deg[idx], 1.0f);
            run += deg[idx];
        }
    }
    if (t == 1023) rowstart[N_NODES] = run;
}

__global__ void fill_csr(const int* __restrict__ ei, int* __restrict__ cursor,
                         int* __restrict__ csrsrc) {
    int e = blockIdx.x * blockDim.x + threadIdx.x;
    if (e < N_EDGES) {
        int dst = ei[N_EDGES + e];
        int p = atomicAdd(cursor + dst, 1);
        csrsrc[p] = ei[e];
    }
}

// ---------------- input projection (+ fused column stats) -------------------
__global__ __launch_bounds__(256) void input_proj(const float* __restrict__ x,
                                                  const float* __restrict__ w,
                                                  const float* __restrict__ b,
                                                  float* __restrict__ out) {
    __shared__ float ws[IN_F * HID];
    __shared__ float xs[16 * IN_F];
    int t = threadIdx.x;
    for (int i = t; i < IN_F * HID; i += 256) ws[i] = w[i];
    int r0 = blockIdx.x * 16;
    int nr = min(16, N_NODES - r0);
    for (int i = t; i < nr * IN_F; i += 256) xs[i] = x[(size_t)r0 * IN_F + i];
    __syncthreads();
    float bb = b[t];
    float s = 0.f, s2 = 0.f;
    for (int r = 0; r < nr; r++) {
        float v = bb;
#pragma unroll
        for (int k = 0; k < IN_F; k++) v += xs[r * IN_F + k] * ws[k * HID + t];
        out[(size_t)(r0 + r) * HID + t] = v;
        s += v; s2 += v * v;
    }
    atomicAdd(&g_stats[t], s);
    atomicAdd(&g_stats[HID + t], s2);
}

// ---------------- BatchNorm params -------------------------------------------
__global__ void zero_stats() {
    g_stats[threadIdx.x] = 0.f;
    g_stats[HID + threadIdx.x] = 0.f;
}

__global__ void bn_finalize(const float* __restrict__ g, const float* __restrict__ be) {
    int c = threadIdx.x;
    float mu  = g_stats[c] * (1.0f / N_NODES);
    float var = g_stats[HID + c] * (1.0f / N_NODES) - mu * mu;
    float sc  = g[c] * rsqrtf(var + BN_EPS);
    g_scale[c] = sc;
    g_shift[c] = be[c] - mu * sc;
}

// ---------------- aggregation: gather-mean of relu(bn(raw)) ------------------
__global__ __launch_bounds__(256) void agg_gather_bn(const int* __restrict__ rowstart,
                                                     const int* __restrict__ csrsrc,
                                                     const float* __restrict__ rcnt,
                                                     const float* __restrict__ raw,
                                                     float* __restrict__ agg) {
    int node = blockIdx.x;
    int c = threadIdx.x;
    float sc = g_scale[c], sh = g_shift[c];
    int j = rowstart[node];
    int e = rowstart[node + 1];
    float acc = 0.f;
    for (; j + 4 <= e; j += 4) {
        int s0 = __ldg(csrsrc + j + 0);
        int s1 = __ldg(csrsrc + j + 1);
        int s2 = __ldg(csrsrc + j + 2);
        int s3 = __ldg(csrsrc + j + 3);
        acc += fmaxf(__ldg(raw + (size_t)s0 * HID + c) * sc + sh, 0.f)
             + fmaxf(__ldg(raw + (size_t)s1 * HID + c) * sc + sh, 0.f)
             + fmaxf(__ldg(raw + (size_t)s2 * HID + c) * sc + sh, 0.f)
             + fmaxf(__ldg(raw + (size_t)s3 * HID + c) * sc + sh, 0.f);
    }
    for (; j < e; j++)
        acc += fmaxf(__ldg(raw + (size_t)__ldg(csrsrc + j) * HID + c) * sc + sh, 0.f);
    agg[(size_t)node * HID + c] = acc * rcnt[node];
}

// ---------------- TF32 mma.sync dual GEMM ------------------------------------
// C = A1 @ W1 + relu(bn(A2raw)) @ W2 + bias; optional fused column stats of C.
__device__ __forceinline__ void mma8(float* c, const uint32_t* a, const uint32_t* b) {
    asm volatile(
        "mma.sync.aligned.m16n8k8.row.col.f32.tf32.tf32.f32 "
        "{%0,%1,%2,%3}, {%4,%5,%6,%7}, {%8,%9}, {%0,%1,%2,%3};"
        : "+f"(c[0]), "+f"(c[1]), "+f"(c[2]), "+f"(c[3])
        : "r"(a[0]), "r"(a[1]), "r"(a[2]), "r"(a[3]), "r"(b[0]), "r"(b[1]));
}

__global__ __launch_bounds__(256, 2) void mma_dual_gemm(
    const float* __restrict__ A1, const float* __restrict__ A2raw,
    const float* __restrict__ W1, const float* __restrict__ W2,
    const float* __restrict__ bias, float* __restrict__ C, int N, int doStats) {
    __shared__ float As[2][16][132];   // [buf][k][m]
    __shared__ float Bs[2][16][132];   // [buf][k][n]

    int tid = threadIdx.x;
    int lane = tid & 31, wid = tid >> 5;
    int g = lane >> 2, tig = lane & 3;
    int wm = (wid & 1) * 64, wn = (wid >> 1) * 32;
    int m0 = blockIdx.x * 128, n0 = blockIdx.y * 128;

    float acc[4][4][4] = {};
    float4 sa[2], sb[2];

#pragma unroll 1
    for (int i = 0; i < 33; i++) {
        // ---- global load for chunk i ----
        if (i < 32) {
            int ph = i >> 4;
            int k0 = (i & 15) * 16;
            const float* A = ph ? A2raw : A1;
            const float* W = ph ? W2 : W1;
#pragma unroll
            for (int q = 0; q < 2; q++) {
                int idx = q * 256 + tid;
                int r = idx >> 2, c4 = (idx & 3) * 4;
                int m = m0 + r;
                float4 v = (m < N_NODES) ? *(const float4*)(A + (size_t)m * HID + k0 + c4)
                                         : make_float4(0.f, 0.f, 0.f, 0.f);
                if (ph) {  // normalize raw h: relu(v*scale+shift), per-k params
                    float4 scv = *(const float4*)(g_scale + k0 + c4);
                    float4 shv = *(const float4*)(g_shift + k0 + c4);
                    v.x = fmaxf(v.x * scv.x + shv.x, 0.f);
                    v.y = fmaxf(v.y * scv.y + shv.y, 0.f);
                    v.z = fmaxf(v.z * scv.z + shv.z, 0.f);
                    v.w = fmaxf(v.w * scv.w + shv.w, 0.f);
                }
                sa[q] = v;
                int kr = idx >> 5, nc = (idx & 31) * 4;
                sb[q] = *(const float4*)(W + (size_t)(k0 + kr) * N + n0 + nc);
            }
        }
        // ---- compute on chunk i-1 ----
        if (i > 0) {
            int buf = (i - 1) & 1;
#pragma unroll
            for (int ks = 0; ks < 2; ks++) {
                int kb = ks * 8;
                uint32_t af[4][4];
#pragma unroll
                for (int mi = 0; mi < 4; mi++) {
                    int m = wm + mi * 16 + g;
                    af[mi][0] = __float_as_uint(As[buf][kb + tig][m]);
                    af[mi][1] = __float_as_uint(As[buf][kb + tig][m + 8]);
                    af[mi][2] = __float_as_uint(As[buf][kb + tig + 4][m]);
                    af[mi][3] = __float_as_uint(As[buf][kb + tig + 4][m + 8]);
                }
                uint32_t bf[4][2];
#pragma unroll
                for (int ni = 0; ni < 4; ni++) {
                    int n = wn + ni * 8 + g;
                    bf[ni][0] = __float_as_uint(Bs[buf][kb + tig][n]);
                    bf[ni][1] = __float_as_uint(Bs[buf][kb + tig + 4][n]);
                }
#pragma unroll
                for (int mi = 0; mi < 4; mi++)
#pragma unroll
                    for (int ni = 0; ni < 4; ni++)
                        mma8(acc[mi][ni], af[mi], bf[ni]);
            }
        }
        // ---- store chunk i into smem ----
        if (i < 32) {
            int buf = i & 1;
            if (i > 0) __syncthreads();
#pragma unroll
            for (int q = 0; q < 2; q++) {
                int idx = q * 256 + tid;
                int r = idx >> 2, c4 = (idx & 3) * 4;
                As[buf][c4 + 0][r] = to_tf32(sa[q].x);
                As[buf][c4 + 1][r] = to_tf32(sa[q].y);
                As[buf][c4 + 2][r] = to_tf32(sa[q].z);
                As[buf][c4 + 3][r] = to_tf32(sa[q].w);
                int kr = idx >> 5, nc = (idx & 31) * 4;
                float4 v;
                v.x = to_tf32(sb[q].x); v.y = to_tf32(sb[q].y);
                v.z = to_tf32(sb[q].z); v.w = to_tf32(sb[q].w);
                *(float4*)&Bs[buf][kr][nc] = v;
            }
            __syncthreads();
        }
    }

    // ---- epilogue: add bias, store, fused column stats ----
#pragma unroll
    for (int ni = 0; ni < 4; ni++) {
        int col = n0 + wn + ni * 8 + tig * 2;
        float b0 = bias[col], b1 = bias[col + 1];
        float s0 = 0.f, s1 = 0.f, q0 = 0.f, q1 = 0.f;
#pragma unroll
        for (int mi = 0; mi < 4; mi++) {
            int row0 = m0 + wm + mi * 16 + g;
            int row1 = row0 + 8;
            float v00 = acc[mi][ni][0] + b0, v01 = acc[mi][ni][1] + b1;
            float v10 = acc[mi][ni][2] + b0, v11 = acc[mi][ni][3] + b1;
            if (row0 < N_NODES) {
                *(float2*)(C + (size_t)row0 * N + col) = make_float2(v00, v01);
                s0 += v00; q0 += v00 * v00; s1 += v01; q1 += v01 * v01;
            }
            if (row1 < N_NODES) {
                *(float2*)(C + (size_t)row1 * N + col) = make_float2(v10, v11);
                s0 += v10; q0 += v10 * v10; s1 += v11; q1 += v11 * v11;
            }
        }
        if (doStats) {
#pragma unroll
            for (int off = 4; off < 32; off <<= 1) {
                s0 += __shfl_xor_sync(0xffffffffu, s0, off);
                s1 += __shfl_xor_sync(0xffffffffu, s1, off);
                q0 += __shfl_xor_sync(0xffffffffu, q0, off);
                q1 += __shfl_xor_sync(0xffffffffu, q1, off);
            }
            if (lane < 4) {
                atomicAdd(&g_stats[col], s0);
                atomicAdd(&g_stats[col + 1], s1);
                atomicAdd(&g_stats[HID + col], q0);
                atomicAdd(&g_stats[HID + col + 1], q1);
            }
        }
    }
}

// ---------------- orchestration ----------------------------------------------
extern "C" void kernel_launch(void* const* d_in, const int* in_sizes, int n_in,
                              void* d_out, int out_size) {
    const float* x    = (const float*)d_in[0];
    const int*   ei   = (const int*)d_in[1];
    const float* w_in = (const float*)d_in[2];
    const float* b_in = (const float*)d_in[3];
    const float* gi   = (const float*)d_in[4];
    const float* bei  = (const float*)d_in[5];
    const float* wl1  = (const float*)d_in[6];
    const float* bl1  = (const float*)d_in[7];
    const float* wr1  = (const float*)d_in[8];
    const float* g1   = (const float*)d_in[9];
    const float* be1  = (const float*)d_in[10];
    const float* wl2  = (const float*)d_in[11];
    const float* bl2  = (const float*)d_in[12];
    const float* wr2  = (const float*)d_in[13];
    const float* g2   = (const float*)d_in[14];
    const float* be2  = (const float*)d_in[15];
    const float* wl3  = (const float*)d_in[16];
    const float* bl3  = (const float*)d_in[17];
    const float* wr3  = (const float*)d_in[18];
    float* out = (float*)d_out;

    float *bufA, *bufB, *bufC, *rcnt;
    int *deg, *rowstart, *cursor, *csrsrc;
    cudaGetSymbolAddress((void**)&bufA, g_bufA);
    cudaGetSymbolAddress((void**)&bufB, g_bufB);
    cudaGetSymbolAddress((void**)&bufC, g_bufC);
    cudaGetSymbolAddress((void**)&rcnt, g_rcnt);
    cudaGetSymbolAddress((void**)&deg, g_deg);
    cudaGetSymbolAddress((void**)&rowstart, g_rowstart);
    cudaGetSymbolAddress((void**)&cursor, g_cursor);
    cudaGetSymbolAddress((void**)&csrsrc, g_csrsrc);

    // ---- CSR build ----
    zero_int<<<(N_NODES + 255) / 256, 256>>>(deg, N_NODES);
    count_deg<<<(N_EDGES + 255) / 256, 256>>>(ei, deg);
    scan_deg<<<1, 1024>>>(deg, rowstart, cursor, rcnt);
    fill_csr<<<(N_EDGES + 255) / 256, 256>>>(ei, cursor, csrsrc);

    // ---- input projection (fused stats) -> bufC raw; bn0 params ----
    zero_stats<<<1, HID>>>();
    input_proj<<<(N_NODES + 15) / 16, 256>>>(x, w_in, b_in, bufC);
    bn_finalize<<<1, HID>>>(gi, bei);

    const int MB = (N_NODES + 127) / 128;  // 391
    dim3 ggrid(MB, HID / 128);             // 391 x 2
    dim3 ogrid(MB, EMB / 128);             // 391 x 1

    // ---- SAGE layer 1: raw=bufC (bn0 applied lazily) -> bufA raw; bn1 ----
    agg_gather_bn<<<N_NODES, 256>>>(rowstart, csrsrc, rcnt, bufC, bufB);
    zero_stats<<<1, HID>>>();
    mma_dual_gemm<<<ggrid, 256>>>(bufB, bufC, wl1, wr1, bl1, bufA, HID, 1);
    bn_finalize<<<1, HID>>>(g1, be1);

    // ---- SAGE layer 2: raw=bufA -> bufC raw; bn2 ----
    agg_gather_bn<<<N_NODES, 256>>>(rowstart, csrsrc, rcnt, bufA, bufB);
    zero_stats<<<1, HID>>>();
    mma_dual_gemm<<<ggrid, 256>>>(bufB, bufA, wl2, wr2, bl2, bufC, HID, 1);
    bn_finalize<<<1, HID>>>(g2, be2);

    // ---- SAGE layer 3: raw=bufC -> out (no BN) ----
    agg_gather_bn<<<N_NODES, 256>>>(rowstart, csrsrc, rcnt, bufC, bufB);
    mma_dual_gemm<<<ogrid, 256>>>(bufB, bufC, wl3, wr3, bl3, out, EMB, 0);
}

// round 8
// speedup vs baseline: 3.9471x; 1.4449x over previous
#include <cuda_runtime.h>
#include <cstdint>

#define N_NODES 50000
#define N_EDGES 800000
#define HID     256
#define EMB     128
#define IN_F    10
#define BN_EPS  1e-5f

// ---------------- scratch (static device globals; no allocation) ------------
__device__ float g_bufA[N_NODES * HID];
__device__ float g_bufB[N_NODES * HID];   // agg (gather target)
__device__ float g_bufC[N_NODES * HID];
__device__ float g_rcnt[N_NODES];
__device__ int   g_deg[N_NODES];
__device__ int   g_rowstart[N_NODES + 1];
__device__ int   g_cursor[N_NODES];
__device__ int   g_csrsrc[N_EDGES];
__device__ float g_stats[2 * HID];
__device__ float g_scale[HID];
__device__ float g_shift[HID];

__device__ __forceinline__ float to_tf32(float x) {
    float y;
    asm("cvt.rna.tf32.f32 %0, %1;" : "=f"(y) : "f"(x));
    return y;
}

// ---------------- CSR construction -----------------------------------------
__global__ void zero_int(int* p, int n) {
    int i = blockIdx.x * blockDim.x + threadIdx.x;
    if (i < n) p[i] = 0;
}

__global__ void count_deg(const int* __restrict__ ei, int* __restrict__ deg) {
    int e = blockIdx.x * blockDim.x + threadIdx.x;
    if (e < N_EDGES) atomicAdd(deg + ei[N_EDGES + e], 1);
}

__global__ __launch_bounds__(1024) void scan_deg(const int* __restrict__ deg,
                                                 int* __restrict__ rowstart,
                                                 int* __restrict__ cursor,
                                                 float* __restrict__ rcnt) {
    __shared__ int partial[1024];
    const int CH = (N_NODES + 1023) / 1024;
    int t = threadIdx.x;
    int base = t * CH;
    int s = 0;
    for (int i = 0; i < CH; i++) {
        int idx = base + i;
        if (idx < N_NODES) s += deg[idx];
    }
    partial[t] = s;
    __syncthreads();
    for (int off = 1; off < 1024; off <<= 1) {
        int v = (t >= off) ? partial[t - off] : 0;
        __syncthreads();
        partial[t] += v;
        __syncthreads();
    }
    int run = (t == 0) ? 0 : partial[t - 1];
    for (int i = 0; i < CH; i++) {
        int idx = base + i;
        if (idx < N_NODES) {
            rowstart[idx] = run;
            cursor[idx] = run;
            rcnt[idx] = 1.0f / fmaxf((float)deg[idx], 1.0f);
            run += deg[idx];
        }
    }
    if (t == 1023) rowstart[N_NODES] = run;
}

__global__ void fill_csr(const int* __restrict__ ei, int* __restrict__ cursor,
                         int* __restrict__ csrsrc) {
    int e = blockIdx.x * blockDim.x + threadIdx.x;
    if (e < N_EDGES) {
        int dst = ei[N_EDGES + e];
        int p = atomicAdd(cursor + dst, 1);
        csrsrc[p] = ei[e];
    }
}

// ---------------- input projection (+ fused column stats) -------------------
__global__ __launch_bounds__(256) void input_proj(const float* __restrict__ x,
                                                  const float* __restrict__ w,
                                                  const float* __restrict__ b,
                                                  float* __restrict__ out) {
    __shared__ float ws[IN_F * HID];
    __shared__ float xs[16 * IN_F];
    int t = threadIdx.x;
    for (int i = t; i < IN_F * HID; i += 256) ws[i] = w[i];
    int r0 = blockIdx.x * 16;
    int nr = min(16, N_NODES - r0);
    for (int i = t; i < nr * IN_F; i += 256) xs[i] = x[(size_t)r0 * IN_F + i];
    __syncthreads();
    float bb = b[t];
    float s = 0.f, s2 = 0.f;
    for (int r = 0; r < nr; r++) {
        float v = bb;
#pragma unroll
        for (int k = 0; k < IN_F; k++) v += xs[r * IN_F + k] * ws[k * HID + t];
        out[(size_t)(r0 + r) * HID + t] = v;
        s += v; s2 += v * v;
    }
    atomicAdd(&g_stats[t], s);
    atomicAdd(&g_stats[HID + t], s2);
}

// ---------------- BatchNorm params -------------------------------------------
__global__ void zero_stats() {
    g_stats[threadIdx.x] = 0.f;
    g_stats[HID + threadIdx.x] = 0.f;
}

__global__ void bn_finalize(const float* __restrict__ g, const float* __restrict__ be) {
    int c = threadIdx.x;
    float mu  = g_stats[c] * (1.0f / N_NODES);
    float var = g_stats[HID + c] * (1.0f / N_NODES) - mu * mu;
    float sc  = g[c] * rsqrtf(var + BN_EPS);
    g_scale[c] = sc;
    g_shift[c] = be[c] - mu * sc;
}

// ---------------- aggregation: gather-mean of relu(bn(raw)) ------------------
// 4 nodes per block, 64 threads/node, float4 per thread (LDG.128).
__global__ __launch_bounds__(256) void agg_gather_bn(const int* __restrict__ rowstart,
                                                     const int* __restrict__ csrsrc,
                                                     const float* __restrict__ rcnt,
                                                     const float* __restrict__ raw,
                                                     float* __restrict__ agg) {
    int node = blockIdx.x * 4 + (threadIdx.x >> 6);
    int c = (threadIdx.x & 63) * 4;
    float4 sc = *(const float4*)(g_scale + c);
    float4 sh = *(const float4*)(g_shift + c);
    int j = rowstart[node];
    int e = rowstart[node + 1];
    float4 acc = make_float4(0.f, 0.f, 0.f, 0.f);
    for (; j + 2 <= e; j += 2) {
        int s0 = __ldg(csrsrc + j);
        int s1 = __ldg(csrsrc + j + 1);
        float4 v0 = *(const float4*)(raw + (size_t)s0 * HID + c);
        float4 v1 = *(const float4*)(raw + (size_t)s1 * HID + c);
        acc.x += fmaxf(v0.x * sc.x + sh.x, 0.f) + fmaxf(v1.x * sc.x + sh.x, 0.f);
        acc.y += fmaxf(v0.y * sc.y + sh.y, 0.f) + fmaxf(v1.y * sc.y + sh.y, 0.f);
        acc.z += fmaxf(v0.z * sc.z + sh.z, 0.f) + fmaxf(v1.z * sc.z + sh.z, 0.f);
        acc.w += fmaxf(v0.w * sc.w + sh.w, 0.f) + fmaxf(v1.w * sc.w + sh.w, 0.f);
    }
    if (j < e) {
        int s0 = __ldg(csrsrc + j);
        float4 v0 = *(const float4*)(raw + (size_t)s0 * HID + c);
        acc.x += fmaxf(v0.x * sc.x + sh.x, 0.f);
        acc.y += fmaxf(v0.y * sc.y + sh.y, 0.f);
        acc.z += fmaxf(v0.z * sc.z + sh.z, 0.f);
        acc.w += fmaxf(v0.w * sc.w + sh.w, 0.f);
    }
    float r = rcnt[node];
    acc.x *= r; acc.y *= r; acc.z *= r; acc.w *= r;
    *(float4*)(agg + (size_t)node * HID + c) = acc;
}

// ---------------- TF32 mma.sync dual GEMM ------------------------------------
// C = A1 @ W1 + relu(bn(A2raw)) @ W2 + bias; optional fused column stats.
// As layout: [m][k] padded to 20 words (STS.128 + conflict-free LDS).
// Bs layout: [k][n] padded to 136 words (conflict-free both ways).
// One __syncthreads per K-chunk.
__device__ __forceinline__ void mma8(float* c, const uint32_t* a, const uint32_t* b) {
    asm volatile(
        "mma.sync.aligned.m16n8k8.row.col.f32.tf32.tf32.f32 "
        "{%0,%1,%2,%3}, {%4,%5,%6,%7}, {%8,%9}, {%0,%1,%2,%3};"
        : "+f"(c[0]), "+f"(c[1]), "+f"(c[2]), "+f"(c[3])
        : "r"(a[0]), "r"(a[1]), "r"(a[2]), "r"(a[3]), "r"(b[0]), "r"(b[1]));
}

__device__ __forceinline__ void load_chunk(const float* __restrict__ A,
                                           const float* __restrict__ W,
                                           int m0, int n0, int k0, int N, int tid,
                                           bool bnA, float4* sa, float4* sb) {
#pragma unroll
    for (int q = 0; q < 2; q++) {
        int idx = q * 256 + tid;
        int r = idx >> 2, c4 = (idx & 3) * 4;
        int m = m0 + r;
        float4 v = (m < N_NODES) ? *(const float4*)(A + (size_t)m * HID + k0 + c4)
                                 : make_float4(0.f, 0.f, 0.f, 0.f);
        if (bnA) {
            float4 scv = *(const float4*)(g_scale + k0 + c4);
            float4 shv = *(const float4*)(g_shift + k0 + c4);
            v.x = fmaxf(v.x * scv.x + shv.x, 0.f);
            v.y = fmaxf(v.y * scv.y + shv.y, 0.f);
            v.z = fmaxf(v.z * scv.z + shv.z, 0.f);
            v.w = fmaxf(v.w * scv.w + shv.w, 0.f);
        }
        sa[q] = v;
        int kr = idx >> 5, nc = (idx & 31) * 4;
        sb[q] = *(const float4*)(W + (size_t)(k0 + kr) * N + n0 + nc);
    }
}

__global__ __launch_bounds__(256, 2) void mma_dual_gemm(
    const float* __restrict__ A1, const float* __restrict__ A2raw,
    const float* __restrict__ W1, const float* __restrict__ W2,
    const float* __restrict__ bias, float* __restrict__ C, int N, int doStats) {
    __shared__ float As[2][128][20];   // [buf][m][k], 20-word rows
    __shared__ float Bs[2][16][136];   // [buf][k][n]

    int tid = threadIdx.x;
    int lane = tid & 31, wid = tid >> 5;
    int g = lane >> 2, tig = lane & 3;
    int wm = (wid & 1) * 64, wn = (wid >> 1) * 32;
    int m0 = blockIdx.x * 128, n0 = blockIdx.y * 128;

    float acc[4][4][4] = {};
    float4 sa[2], sb[2];

    // prologue: load chunk 0 (phase 0, k0 = 0)
    load_chunk(A1, W1, m0, n0, 0, N, tid, false, sa, sb);

#pragma unroll 1
    for (int i = 0; i < 32; i++) {
        int buf = i & 1;
        // ---- store chunk i to smem ----
#pragma unroll
        for (int q = 0; q < 2; q++) {
            int idx = q * 256 + tid;
            int r = idx >> 2, c4 = (idx & 3) * 4;
            float4 v;
            v.x = to_tf32(sa[q].x); v.y = to_tf32(sa[q].y);
            v.z = to_tf32(sa[q].z); v.w = to_tf32(sa[q].w);
            *(float4*)&As[buf][r][c4] = v;
            int kr = idx >> 5, nc = (idx & 31) * 4;
            float4 w;
            w.x = to_tf32(sb[q].x); w.y = to_tf32(sb[q].y);
            w.z = to_tf32(sb[q].z); w.w = to_tf32(sb[q].w);
            *(float4*)&Bs[buf][kr][nc] = w;
        }
        // ---- issue global loads for chunk i+1 ----
        if (i + 1 < 32) {
            int ph = (i + 1) >> 4;
            int k0 = ((i + 1) & 15) * 16;
            load_chunk(ph ? A2raw : A1, ph ? W2 : W1, m0, n0, k0, N, tid,
                       ph != 0, sa, sb);
        }
        __syncthreads();
        // ---- compute chunk i ----
#pragma unroll
        for (int ks = 0; ks < 2; ks++) {
            int kb = ks * 8;
            uint32_t af[4][4];
#pragma unroll
            for (int mi = 0; mi < 4; mi++) {
                int m = wm + mi * 16 + g;
                af[mi][0] = __float_as_uint(As[buf][m][kb + tig]);
                af[mi][1] = __float_as_uint(As[buf][m + 8][kb + tig]);
                af[mi][2] = __float_as_uint(As[buf][m][kb + tig + 4]);
                af[mi][3] = __float_as_uint(As[buf][m + 8][kb + tig + 4]);
            }
            uint32_t bf[4][2];
#pragma unroll
            for (int ni = 0; ni < 4; ni++) {
                int n = wn + ni * 8 + g;
                bf[ni][0] = __float_as_uint(Bs[buf][kb + tig][n]);
                bf[ni][1] = __float_as_uint(Bs[buf][kb + tig + 4][n]);
            }
#pragma unroll
            for (int mi = 0; mi < 4; mi++)
#pragma unroll
                for (int ni = 0; ni < 4; ni++)
                    mma8(acc[mi][ni], af[mi], bf[ni]);
        }
    }

    // ---- epilogue: add bias, store, fused column stats ----
#pragma unroll
    for (int ni = 0; ni < 4; ni++) {
        int col = n0 + wn + ni * 8 + tig * 2;
        float b0 = bias[col], b1 = bias[col + 1];
        float s0 = 0.f, s1 = 0.f, q0 = 0.f, q1 = 0.f;
#pragma unroll
        for (int mi = 0; mi < 4; mi++) {
            int row0 = m0 + wm + mi * 16 + g;
            int row1 = row0 + 8;
            float v00 = acc[mi][ni][0] + b0, v01 = acc[mi][ni][1] + b1;
            float v10 = acc[mi][ni][2] + b0, v11 = acc[mi][ni][3] + b1;
            if (row0 < N_NODES) {
                *(float2*)(C + (size_t)row0 * N + col) = make_float2(v00, v01);
                s0 += v00; q0 += v00 * v00; s1 += v01; q1 += v01 * v01;
            }
            if (row1 < N_NODES) {
                *(float2*)(C + (size_t)row1 * N + col) = make_float2(v10, v11);
                s0 += v10; q0 += v10 * v10; s1 += v11; q1 += v11 * v11;
            }
        }
        if (doStats) {
#pragma unroll
            for (int off = 4; off < 32; off <<= 1) {
                s0 += __shfl_xor_sync(0xffffffffu, s0, off);
                s1 += __shfl_xor_sync(0xffffffffu, s1, off);
                q0 += __shfl_xor_sync(0xffffffffu, q0, off);
                q1 += __shfl_xor_sync(0xffffffffu, q1, off);
            }
            if (lane < 4) {
                atomicAdd(&g_stats[col], s0);
                atomicAdd(&g_stats[col + 1], s1);
                atomicAdd(&g_stats[HID + col], q0);
                atomicAdd(&g_stats[HID + col + 1], q1);
            }
        }
    }
}

// ---------------- orchestration ----------------------------------------------
extern "C" void kernel_launch(void* const* d_in, const int* in_sizes, int n_in,
                              void* d_out, int out_size) {
    const float* x    = (const float*)d_in[0];
    const int*   ei   = (const int*)d_in[1];
    const float* w_in = (const float*)d_in[2];
    const float* b_in = (const float*)d_in[3];
    const float* gi   = (const float*)d_in[4];
    const float* bei  = (const float*)d_in[5];
    const float* wl1  = (const float*)d_in[6];
    const float* bl1  = (const float*)d_in[7];
    const float* wr1  = (const float*)d_in[8];
    const float* g1   = (const float*)d_in[9];
    const float* be1  = (const float*)d_in[10];
    const float* wl2  = (const float*)d_in[11];
    const float* bl2  = (const float*)d_in[12];
    const float* wr2  = (const float*)d_in[13];
    const float* g2   = (const float*)d_in[14];
    const float* be2  = (const float*)d_in[15];
    const float* wl3  = (const float*)d_in[16];
    const float* bl3  = (const float*)d_in[17];
    const float* wr3  = (const float*)d_in[18];
    float* out = (float*)d_out;

    float *bufA, *bufB, *bufC, *rcnt;
    int *deg, *rowstart, *cursor, *csrsrc;
    cudaGetSymbolAddress((void**)&bufA, g_bufA);
    cudaGetSymbolAddress((void**)&bufB, g_bufB);
    cudaGetSymbolAddress((void**)&bufC, g_bufC);
    cudaGetSymbolAddress((void**)&rcnt, g_rcnt);
    cudaGetSymbolAddress((void**)&deg, g_deg);
    cudaGetSymbolAddress((void**)&rowstart, g_rowstart);
    cudaGetSymbolAddress((void**)&cursor, g_cursor);
    cudaGetSymbolAddress((void**)&csrsrc, g_csrsrc);

    // ---- CSR build ----
    zero_int<<<(N_NODES + 255) / 256, 256>>>(deg, N_NODES);
    count_deg<<<(N_EDGES + 255) / 256, 256>>>(ei, deg);
    scan_deg<<<1, 1024>>>(deg, rowstart, cursor, rcnt);
    fill_csr<<<(N_EDGES + 255) / 256, 256>>>(ei, cursor, csrsrc);

    // ---- input projection (fused stats) -> bufC raw; bn0 params ----
    zero_stats<<<1, HID>>>();
    input_proj<<<(N_NODES + 15) / 16, 256>>>(x, w_in, b_in, bufC);
    bn_finalize<<<1, HID>>>(gi, bei);

    const int MB = (N_NODES + 127) / 128;  // 391
    dim3 ggrid(MB, HID / 128);             // 391 x 2
    dim3 ogrid(MB, EMB / 128);             // 391 x 1
    const int AGG_BLOCKS = N_NODES / 4;    // 12500

    // ---- SAGE layer 1: raw=bufC (bn0 lazily) -> bufA raw; bn1 ----
    agg_gather_bn<<<AGG_BLOCKS, 256>>>(rowstart, csrsrc, rcnt, bufC, bufB);
    zero_stats<<<1, HID>>>();
    mma_dual_gemm<<<ggrid, 256>>>(bufB, bufC, wl1, wr1, bl1, bufA, HID, 1);
    bn_finalize<<<1, HID>>>(g1, be1);

    // ---- SAGE layer 2: raw=bufA -> bufC raw; bn2 ----
    agg_gather_bn<<<AGG_BLOCKS, 256>>>(rowstart, csrsrc, rcnt, bufA, bufB);
    zero_stats<<<1, HID>>>();
    mma_dual_gemm<<<ggrid, 256>>>(bufB, bufA, wl2, wr2, bl2, bufC, HID, 1);
    bn_finalize<<<1, HID>>>(g2, be2);

    // ---- SAGE layer 3: raw=bufC -> out (no BN) ----
    agg_gather_bn<<<AGG_BLOCKS, 256>>>(rowstart, csrsrc, rcnt, bufC, bufB);
    mma_dual_gemm<<<ogrid, 256>>>(bufB, bufC, wl3, wr3, bl3, out, EMB, 0);
}